// round 4
// baseline (speedup 1.0000x reference)
#include <cuda_runtime.h>
#include <cuda_bf16.h>

// Problem constants (fixed by the dataset)
#define B    256
#define G    20000
#define NTF  1024
#define NPT  8     // nodes per TF
#define GPT  64    // genes per TF
#define EPS  1e-5f
#define SLOPE 0.01f

typedef unsigned long long u64;

// Packed fp32x2 FMA (Blackwell): d = a*b + d, elementwise on 2 packed floats.
#define FMA2(d, a, b) asm("fma.rn.f32x2 %0, %1, %2, %0;" : "+l"(d) : "l"(a), "l"(b))
#define UNPACK2(lo, hi, v) asm("mov.b64 {%0, %1}, %2;" : "=f"(lo), "=f"(hi) : "l"(v))

// Scratch: x transposed to [G, B] for coalesced gene-row gathers. 20.48 MB.
__device__ float g_xT[(size_t)G * B];

// ---------------------------------------------------------------------------
// Kernel 1: transpose x [B, G] -> xT [G, B].  G = 625 * 32 exactly.
// ---------------------------------------------------------------------------
__global__ void __launch_bounds__(256) transpose_kernel(const float* __restrict__ x) {
    __shared__ float tile[32][33];
    const int g0 = blockIdx.x * 32;
    const int b0 = blockIdx.y * 32;
    const int tx = threadIdx.x;      // 0..31
    const int ty = threadIdx.y;      // 0..7

#pragma unroll
    for (int i = 0; i < 32; i += 8)
        tile[ty + i][tx] = x[(size_t)(b0 + ty + i) * G + (g0 + tx)];
    __syncthreads();
#pragma unroll
    for (int i = 0; i < 32; i += 8)
        g_xT[(size_t)(g0 + ty + i) * B + (b0 + tx)] = tile[tx][ty + i];
}

// ---------------------------------------------------------------------------
// Kernel 2: fused encoder. One 128-thread block per TF (grid = 1024).
//   Each thread owns 2 batch elements, held as ONE packed f32x2 value.
//   Layer-1 inner loop uses fma.rn.f32x2 with pre-duplicated {w,w} weights
//   from smem and double-buffered 4-gene gather prefetch.
// ---------------------------------------------------------------------------
__global__ void __launch_bounds__(128, 8) fused_encoder_kernel(
    const float* __restrict__ w1,
    const int*   __restrict__ in_idx1,
    const float* __restrict__ w2,
    float*       __restrict__ out)
{
    const int tid  = threadIdx.x;     // 0..127
    const int wrp  = tid >> 5;        // 0..3
    const int lane = tid & 31;
    const int t    = blockIdx.x;

    __shared__ __align__(16) float2 sw1d[NPT * GPT];  // [g*8 + j] = {w, w}
    __shared__ int   sg[GPT];                         // gene offsets * B
    __shared__ float sw2[NPT];
    __shared__ float rsum[4][NPT + 2];                // per-warp partials
    __shared__ float rsq [4][NPT + 2];
    __shared__ float smean[NPT], srstd[NPT];
    __shared__ float zmean, zrstd;

    // ---- Stage duplicated weights + gene indices -----------------------------
#pragma unroll
    for (int i = tid; i < NPT * GPT; i += 128) {
        const int j = i >> 6;          // node
        const int g = i & 63;          // gene slot
        const float w = w1[t * (NPT * GPT) + i];
        sw1d[g * NPT + j] = make_float2(w, w);
    }
    if (tid < GPT) sg[tid]  = in_idx1[t * (NPT * GPT) + tid] * B;
    if (tid < NPT) sw2[tid] = w2[t * NPT + tid];
    __syncthreads();

    // ---- Layer 1: acc2[j] = packed pair over 2 batch elems -------------------
    u64 acc2[NPT];
#pragma unroll
    for (int j = 0; j < NPT; j++) acc2[j] = 0ull;     // (0.f, 0.f)

    const int boff = 2 * tid;

    // per-gene FMA: 4 LDS.128 of duplicated weights + 8 FFMA2
#define GENE_FMA(gidx, xv)                                                     \
    {                                                                          \
        const ulonglong2 w01 = *(const ulonglong2*)&sw1d[(gidx) * NPT + 0];    \
        const ulonglong2 w23 = *(const ulonglong2*)&sw1d[(gidx) * NPT + 2];    \
        const ulonglong2 w45 = *(const ulonglong2*)&sw1d[(gidx) * NPT + 4];    \
        const ulonglong2 w67 = *(const ulonglong2*)&sw1d[(gidx) * NPT + 6];    \
        FMA2(acc2[0], w01.x, (xv)); FMA2(acc2[1], w01.y, (xv));                \
        FMA2(acc2[2], w23.x, (xv)); FMA2(acc2[3], w23.y, (xv));                \
        FMA2(acc2[4], w45.x, (xv)); FMA2(acc2[5], w45.y, (xv));                \
        FMA2(acc2[6], w67.x, (xv)); FMA2(acc2[7], w67.y, (xv));                \
    }

    u64 xa[4], xb[4];
#pragma unroll
    for (int u = 0; u < 4; u++)
        xa[u] = *(const u64*)&g_xT[sg[u] + boff];

#pragma unroll
    for (int g0 = 0; g0 < GPT; g0 += 8) {
        // prefetch genes g0+4 .. g0+7
#pragma unroll
        for (int u = 0; u < 4; u++)
            xb[u] = *(const u64*)&g_xT[sg[g0 + 4 + u] + boff];
        // compute genes g0 .. g0+3
#pragma unroll
        for (int u = 0; u < 4; u++) GENE_FMA(g0 + u, xa[u]);
        // prefetch genes g0+8 .. g0+11
        if (g0 + 8 < GPT) {
#pragma unroll
            for (int u = 0; u < 4; u++)
                xa[u] = *(const u64*)&g_xT[sg[g0 + 8 + u] + boff];
        }
        // compute genes g0+4 .. g0+7
#pragma unroll
        for (int u = 0; u < 4; u++) GENE_FMA(g0 + 4 + u, xb[u]);
    }

    // unpack accumulators
    float2 acc[NPT];
#pragma unroll
    for (int j = 0; j < NPT; j++) UNPACK2(acc[j].x, acc[j].y, acc2[j]);

    // ---- BN1 stats: sum over 256 batch elems (128 threads x 2) per node ------
#pragma unroll
    for (int j = 0; j < NPT; j++) {
        float s  = acc[j].x + acc[j].y;
        float s2 = acc[j].x * acc[j].x + acc[j].y * acc[j].y;
#pragma unroll
        for (int o = 16; o > 0; o >>= 1) {
            s  += __shfl_xor_sync(0xffffffffu, s,  o);
            s2 += __shfl_xor_sync(0xffffffffu, s2, o);
        }
        if (lane == 0) { rsum[wrp][j] = s; rsq[wrp][j] = s2; }
    }
    __syncthreads();
    if (tid < NPT) {
        float s = 0.f, s2 = 0.f;
#pragma unroll
        for (int w = 0; w < 4; w++) { s += rsum[w][tid]; s2 += rsq[w][tid]; }
        const float m   = s * (1.f / B);
        const float var = s2 * (1.f / B) - m * m;
        smean[tid] = m;
        srstd[tid] = rsqrtf(var + EPS);
    }
    __syncthreads();

    // ---- BN1 + LeakyReLU + Layer 2 dot ---------------------------------------
    float z0 = 0.f, z1 = 0.f;
#pragma unroll
    for (int j = 0; j < NPT; j++) {
        const float m = smean[j], r = srstd[j], w = sw2[j];
        float v0 = (acc[j].x - m) * r;  v0 = (v0 > 0.f) ? v0 : SLOPE * v0;
        float v1 = (acc[j].y - m) * r;  v1 = (v1 > 0.f) ? v1 : SLOPE * v1;
        z0 = fmaf(w, v0, z0);
        z1 = fmaf(w, v1, z1);
    }

    // ---- BN2 stats over 256 batch values -------------------------------------
    {
        float s = z0 + z1, s2 = z0 * z0 + z1 * z1;
#pragma unroll
        for (int o = 16; o > 0; o >>= 1) {
            s  += __shfl_xor_sync(0xffffffffu, s,  o);
            s2 += __shfl_xor_sync(0xffffffffu, s2, o);
        }
        if (lane == 0) { rsum[wrp][NPT] = s; rsq[wrp][NPT] = s2; }
    }
    __syncthreads();
    if (tid == 0) {
        float s = 0.f, s2 = 0.f;
#pragma unroll
        for (int w = 0; w < 4; w++) { s += rsum[w][NPT]; s2 += rsq[w][NPT]; }
        const float m   = s * (1.f / B);
        const float var = s2 * (1.f / B) - m * m;
        zmean = m;
        zrstd = rsqrtf(var + EPS);
    }
    __syncthreads();

    const float m = zmean, r = zrstd;
    float v0 = (z0 - m) * r;  v0 = (v0 > 0.f) ? v0 : SLOPE * v0;
    float v1 = (z1 - m) * r;  v1 = (v1 > 0.f) ? v1 : SLOPE * v1;
    out[(size_t)(boff)     * NTF + t] = v0;
    out[(size_t)(boff + 1) * NTF + t] = v1;
}

// ---------------------------------------------------------------------------
extern "C" void kernel_launch(void* const* d_in, const int* in_sizes, int n_in,
                              void* d_out, int out_size) {
    const float* x       = (const float*)d_in[0];
    const float* w1      = (const float*)d_in[1];
    const int*   in_idx1 = (const int*)  d_in[2];
    const float* w2      = (const float*)d_in[4];
    float*       out     = (float*)d_out;

    dim3 tb(32, 8);
    dim3 tg(G / 32, B / 32);           // 625 x 8, exact
    transpose_kernel<<<tg, tb>>>(x);
    fused_encoder_kernel<<<NTF, 128>>>(w1, in_idx1, w2, out);
}